// round 1
// baseline (speedup 1.0000x reference)
#include <cuda_runtime.h>
#include <cstdint>

#define Bn 4
#define Sn 80
#define Pn 6500
#define Fdim 128
#define Hdim 128
#define PSPLIT 4
#define PCHUNK 1625   // 6500 / 4

// ---------------- scratch (device globals; no allocation allowed) ----------------
__device__ float d_embpart[PSPLIT][Bn * Sn][Fdim];     // partial per-feature maxes
__device__ float d_xg[2][Bn][Sn][4 * Hdim];            // precomputed LSTM input gates
__device__ float d_hfinal[2][Bn][Hdim];                // final hidden per direction

// ---------------- helpers ----------------
__device__ __forceinline__ uint32_t smem_u32_(const void* p) {
    return (uint32_t)__cvta_generic_to_shared(p);
}
__device__ __forceinline__ uint32_t mapa_rank_(uint32_t a, uint32_t r) {
    uint32_t d;
    asm("mapa.shared::cluster.u32 %0, %1, %2;" : "=r"(d) : "r"(a), "r"(r));
    return d;
}
__device__ __forceinline__ void stc_f32_(uint32_t a, float v) {
    asm volatile("st.shared::cluster.f32 [%0], %1;" :: "r"(a), "f"(v) : "memory");
}
__device__ __forceinline__ void cluster_sync_() {
    asm volatile("barrier.cluster.arrive.aligned;" ::: "memory");
    asm volatile("barrier.cluster.wait.aligned;" ::: "memory");
}
__device__ __forceinline__ float sigmoid_(float x) {
    return 1.0f / (1.0f + expf(-x));
}

// =============================================================================
// Kernel 1: per-point MLP (2->64->128) + masked max over a P-chunk.
// grid (B*S, PSPLIT), 256 threads. Register-tiled 8x8 GEMM on smem tiles.
// emb >= 0 always, so partial max init 0 is exact (incl. all-masked case).
// =============================================================================
__global__ __launch_bounds__(256) void k1_pointmlp(
    const float* __restrict__ slices, const float* __restrict__ pmask,
    const float* __restrict__ W1, const float* __restrict__ b1,
    const float* __restrict__ W2, const float* __restrict__ b2)
{
    extern __shared__ float sm[];
    float* W2s = sm;              // [64][132] k-major, padded
    float* hs  = sm + 8448;       // [64][132] hidden tile, k-major
    float* b2s = sm + 16896;      // 128
    float* xs  = sm + 17024;      // 128
    float* ys  = sm + 17152;      // 128
    float* msk = sm + 17280;      // 128
    float* w1x = sm + 17408;      // 64
    float* w1y = sm + 17472;      // 64
    float* b1s = sm + 17536;      // 64  (total 17600 floats = 70400 B)

    const int tid = threadIdx.x;
    const int bs  = blockIdx.x;

    for (int idx = tid; idx < 8192; idx += 256) {
        int f = idx >> 6, k = idx & 63;
        W2s[k * 132 + f] = W2[idx];            // W2 is [128][64] row-major
    }
    if (tid < 128) b2s[tid] = b2[tid];
    if (tid < 64) { w1x[tid] = W1[2 * tid]; w1y[tid] = W1[2 * tid + 1]; b1s[tid] = b1[tid]; }
    __syncthreads();

    const int tx = tid & 15, ty = tid >> 4;
    const int f0 = ty * 8, q0 = tx * 8;

    float b2r[8];
#pragma unroll
    for (int i = 0; i < 8; i++) b2r[i] = b2s[f0 + i];
    float wmax[8];
#pragma unroll
    for (int i = 0; i < 8; i++) wmax[i] = 0.f;

    const float* sp = slices + (size_t)bs * Pn * 2;
    const float* mp = pmask + (size_t)bs * Pn;
    const int pbeg = blockIdx.y * PCHUNK;
    const int pend = pbeg + PCHUNK;

    for (int base = pbeg; base < pend; base += 128) {
        // load point coords + mask (tail-guarded; padded points get mask 0)
        if (tid < 128) {
            int p = base + tid;
            float x = 0.f, y = 0.f, m = 0.f;
            if (p < pend) { x = sp[2 * p]; y = sp[2 * p + 1]; m = mp[p]; }
            xs[tid] = x; ys[tid] = y; msk[tid] = m;
        }
        __syncthreads();

        // hidden layer: h[j][p] = relu(W1 row j . (x,y) + b1)
        {
            int pp = tid & 127;
            int jb = (tid >> 7) * 32;
            float x = xs[pp], y = ys[pp];
#pragma unroll 8
            for (int j = jb; j < jb + 32; ++j) {
                float v = fmaf(w1x[j], x, fmaf(w1y[j], y, b1s[j]));
                hs[j * 132 + pp] = fmaxf(v, 0.f);
            }
        }
        __syncthreads();

        // 128x128 output tile: acc[feature 8][point 8]
        float acc[8][8];
#pragma unroll
        for (int i = 0; i < 8; i++)
#pragma unroll
            for (int j = 0; j < 8; j++) acc[i][j] = 0.f;

#pragma unroll 4
        for (int k = 0; k < 64; k++) {
            float4 w0 = *(const float4*)(W2s + k * 132 + f0);
            float4 w1v = *(const float4*)(W2s + k * 132 + f0 + 4);
            float4 a0 = *(const float4*)(hs + k * 132 + q0);
            float4 a1 = *(const float4*)(hs + k * 132 + q0 + 4);
            float w[8] = {w0.x, w0.y, w0.z, w0.w, w1v.x, w1v.y, w1v.z, w1v.w};
            float a[8] = {a0.x, a0.y, a0.z, a0.w, a1.x, a1.y, a1.z, a1.w};
#pragma unroll
            for (int i = 0; i < 8; i++)
#pragma unroll
                for (int j = 0; j < 8; j++)
                    acc[i][j] = fmaf(w[i], a[j], acc[i][j]);
        }

        // epilogue: bias + relu + mask, fold into running max
#pragma unroll
        for (int j = 0; j < 8; j++) {
            float mk = msk[q0 + j];
#pragma unroll
            for (int i = 0; i < 8; i++) {
                float v = fmaxf(acc[i][j] + b2r[i], 0.f) * mk;
                wmax[i] = fmaxf(wmax[i], v);
            }
        }
        __syncthreads();
    }

    // reduce max across the 16 point-groups (tx), reuse hs as scratch
    float* red = hs;
#pragma unroll
    for (int i = 0; i < 8; i++) red[tx * 128 + f0 + i] = wmax[i];
    __syncthreads();
    if (tid < 128) {
        float m = 0.f;
#pragma unroll
        for (int r = 0; r < 16; r++) m = fmaxf(m, red[r * 128 + tid]);
        d_embpart[blockIdx.y][bs][tid] = m;
    }
}

// =============================================================================
// Kernel 2: emb = max over partials; xg[dir][b][t][g] = emb . Wi[g] + bi + bh
// (backward direction stored time-reversed so kernel 3 scans forward)
// =============================================================================
__global__ __launch_bounds__(128) void k2_inputgates(
    const float* __restrict__ Wi_f, const float* __restrict__ bi_f, const float* __restrict__ bh_f,
    const float* __restrict__ Wi_b, const float* __restrict__ bi_b, const float* __restrict__ bh_b)
{
    __shared__ float embs[128];
    const int tid = threadIdx.x;
    const int bs = blockIdx.x;
    const int b = bs / Sn, s = bs % Sn;

    float m = d_embpart[0][bs][tid];
    m = fmaxf(m, d_embpart[1][bs][tid]);
    m = fmaxf(m, d_embpart[2][bs][tid]);
    m = fmaxf(m, d_embpart[3][bs][tid]);
    embs[tid] = m;
    __syncthreads();

#pragma unroll
    for (int dir = 0; dir < 2; dir++) {
        const float* Wi = dir ? Wi_b : Wi_f;
        const float* bi = dir ? bi_b : bi_f;
        const float* bh = dir ? bh_b : bh_f;
        const int t = dir ? (Sn - 1 - s) : s;
#pragma unroll
        for (int rr = 0; rr < 4; rr++) {
            int g = rr * 128 + tid;
            const float* wr = Wi + (size_t)g * 128;
            float a = bi[g] + bh[g];
#pragma unroll 8
            for (int k = 0; k < 128; k += 4) {
                float4 w = *(const float4*)(wr + k);
                a = fmaf(w.x, embs[k], a);
                a = fmaf(w.y, embs[k + 1], a);
                a = fmaf(w.z, embs[k + 2], a);
                a = fmaf(w.w, embs[k + 3], a);
            }
            d_xg[dir][b][t][g] = a;
        }
    }
}

// =============================================================================
// Kernel 3: LSTM scan. Cluster of 4 CTAs per direction; rank r holds gate rows
// [r*128, r*128+128) of Wh in SMEM (fp32, 66KB). Each step:
//   all ranks: partial gemm (own 128 rows x 4 batches x K=128) + activation,
//              DSMEM-write activated gates to rank 0
//   rank 0:    c/h update, DSMEM-broadcast new h to all ranks
// rank order = gate order of jnp.split: 0=i, 1=f, 2=g(tanh), 3=o
// =============================================================================
__global__ void __cluster_dims__(4, 1, 1) __launch_bounds__(128, 1)
k3_lstm(const float* __restrict__ Wh_f, const float* __restrict__ Wh_b)
{
    extern __shared__ float sm3[];
    float* Whs  = sm3;            // [128][132]
    float* hbuf = sm3 + 16896;    // [4][128]
    float* gact = sm3 + 17408;    // [4 ranks][4 b][128]   (used on rank 0)

    const int t = threadIdx.x;            // local gate row / hidden unit
    const int rank = blockIdx.x & 3;
    const int dir  = blockIdx.x >> 2;
    const float* Wh = dir ? Wh_b : Wh_f;

    const int R = rank * 128 + t;
    const float* wr = Wh + (size_t)R * 128;
#pragma unroll 8
    for (int k = 0; k < 128; k += 4)
        *(float4*)(Whs + t * 132 + k) = *(const float4*)(wr + k);
    for (int i = t; i < 512; i += 128) hbuf[i] = 0.f;

    float c[Bn];
#pragma unroll
    for (int b = 0; b < Bn; b++) c[b] = 0.f;

    // precompute DSMEM addresses
    uint32_t ga_rem[Bn];
#pragma unroll
    for (int b = 0; b < Bn; b++)
        ga_rem[b] = mapa_rank_(smem_u32_(&gact[(rank * Bn + b) * 128 + t]), 0);
    uint32_t hb_rem[4][Bn];
#pragma unroll
    for (int r = 0; r < 4; r++)
#pragma unroll
        for (int b = 0; b < Bn; b++)
            hb_rem[r][b] = mapa_rank_(smem_u32_(&hbuf[b * 128 + t]), (uint32_t)r);

    __syncthreads();
    cluster_sync_();

    for (int st = 0; st < Sn; ++st) {
        // prefetch input-gate contributions (independent of h)
        float xin[Bn];
#pragma unroll
        for (int b = 0; b < Bn; b++) xin[b] = d_xg[dir][b][st][rank * 128 + t];

        float acc[Bn];
#pragma unroll
        for (int b = 0; b < Bn; b++) acc[b] = 0.f;
#pragma unroll 4
        for (int k = 0; k < 128; k += 4) {
            float4 w = *(const float4*)(Whs + t * 132 + k);
#pragma unroll
            for (int b = 0; b < Bn; b++) {
                float4 hv = *(const float4*)(hbuf + b * 128 + k);
                acc[b] = fmaf(w.x, hv.x, acc[b]);
                acc[b] = fmaf(w.y, hv.y, acc[b]);
                acc[b] = fmaf(w.z, hv.z, acc[b]);
                acc[b] = fmaf(w.w, hv.w, acc[b]);
            }
        }

#pragma unroll
        for (int b = 0; b < Bn; b++) {
            float g = acc[b] + xin[b];
            float av = (rank == 2) ? tanhf(g) : sigmoid_(g);
            stc_f32_(ga_rem[b], av);
        }
        cluster_sync_();

        if (rank == 0) {
#pragma unroll
            for (int b = 0; b < Bn; b++) {
                float iv = gact[(0 * Bn + b) * 128 + t];
                float fv = gact[(1 * Bn + b) * 128 + t];
                float gv = gact[(2 * Bn + b) * 128 + t];
                float ov = gact[(3 * Bn + b) * 128 + t];
                float cn = fmaf(fv, c[b], iv * gv);
                c[b] = cn;
                float hv = ov * tanhf(cn);
#pragma unroll
                for (int r = 0; r < 4; r++) stc_f32_(hb_rem[r][b], hv);
            }
        }
        cluster_sync_();
    }

    if (rank == 0) {
#pragma unroll
        for (int b = 0; b < Bn; b++) d_hfinal[dir][b][t] = hbuf[b * 128 + t];
    }
}

// =============================================================================
// Kernel 4: head: out[b] = W4 . relu(W3 @ [h_fwd; h_bwd] + b3) + b4
// =============================================================================
__global__ __launch_bounds__(128) void k4_head(
    const float* __restrict__ W3, const float* __restrict__ b3,
    const float* __restrict__ W4, const float* __restrict__ b4,
    float* __restrict__ out)
{
    __shared__ float sf[Bn][256];
    __shared__ float red[128];
    const int tid = threadIdx.x;

    for (int idx = tid; idx < Bn * 128; idx += 128) {
        int b = idx >> 7, j = idx & 127;
        sf[b][j]       = d_hfinal[0][b][j];
        sf[b][128 + j] = d_hfinal[1][b][j];
    }
    __syncthreads();

    const float* w3r = W3 + (size_t)tid * 256;
    const float w4v = W4[tid];

    for (int b = 0; b < Bn; b++) {
        float a = b3[tid];
#pragma unroll 8
        for (int k = 0; k < 256; k += 4) {
            float4 w = *(const float4*)(w3r + k);
            a = fmaf(w.x, sf[b][k], a);
            a = fmaf(w.y, sf[b][k + 1], a);
            a = fmaf(w.z, sf[b][k + 2], a);
            a = fmaf(w.w, sf[b][k + 3], a);
        }
        float v = fmaxf(a, 0.f) * w4v;
        red[tid] = v;
        __syncthreads();
        for (int off = 64; off > 0; off >>= 1) {
            if (tid < off) red[tid] += red[tid + off];
            __syncthreads();
        }
        if (tid == 0) out[b] = red[0] + b4[0];
        __syncthreads();
    }
}

// =============================================================================
extern "C" void kernel_launch(void* const* d_in, const int* in_sizes, int n_in,
                              void* d_out, int out_size)
{
    const float* slices = (const float*)d_in[0];
    const float* pmask  = (const float*)d_in[1];
    const float* W1   = (const float*)d_in[2];
    const float* b1   = (const float*)d_in[3];
    const float* W2   = (const float*)d_in[4];
    const float* b2   = (const float*)d_in[5];
    const float* Wi_f = (const float*)d_in[6];
    const float* Wh_f = (const float*)d_in[7];
    const float* bi_f = (const float*)d_in[8];
    const float* bh_f = (const float*)d_in[9];
    const float* Wi_b = (const float*)d_in[10];
    const float* Wh_b = (const float*)d_in[11];
    const float* bi_b = (const float*)d_in[12];
    const float* bh_b = (const float*)d_in[13];
    const float* W3   = (const float*)d_in[14];
    const float* b3   = (const float*)d_in[15];
    const float* W4   = (const float*)d_in[16];
    const float* b4   = (const float*)d_in[17];
    float* out = (float*)d_out;

    cudaFuncSetAttribute(k1_pointmlp, cudaFuncAttributeMaxDynamicSharedMemorySize, 70400);
    cudaFuncSetAttribute(k3_lstm,     cudaFuncAttributeMaxDynamicSharedMemorySize, 77824);

    k1_pointmlp<<<dim3(Bn * Sn, PSPLIT), 256, 70400>>>(slices, pmask, W1, b1, W2, b2);
    k2_inputgates<<<Bn * Sn, 128>>>(Wi_f, bi_f, bh_f, Wi_b, bi_b, bh_b);
    k3_lstm<<<8, 128, 77824>>>(Wh_f, Wh_b);
    k4_head<<<1, 128>>>(W3, b3, W4, b4, out);
}

// round 3
// speedup vs baseline: 1.7313x; 1.7313x over previous
#include <cuda_runtime.h>
#include <cuda_bf16.h>
#include <cstdint>

#define Bn 4
#define Sn 80
#define Pn 6500
#define Hdim 128
#define PSPLIT 4
#define PCHUNK 1625   // 6500 / 4
#define NT1 13        // ceil(1625/128)
#define RS 35         // SMEM row stride in 32-bit words (70 bf16) — conflict-free

// ---------------- scratch ----------------
__device__ float d_embpart[PSPLIT][Bn * Sn][128];
__device__ float d_xg[2][Bn][Sn][4 * Hdim];
__device__ float d_hfinal[2][Bn][Hdim];

// ---------------- helpers ----------------
__device__ __forceinline__ uint32_t smem_u32_(const void* p) {
    return (uint32_t)__cvta_generic_to_shared(p);
}
__device__ __forceinline__ uint32_t mapa_rank_(uint32_t a, uint32_t r) {
    uint32_t d;
    asm("mapa.shared::cluster.u32 %0, %1, %2;" : "=r"(d) : "r"(a), "r"(r));
    return d;
}
__device__ __forceinline__ void stc_f32_(uint32_t a, float v) {
    asm volatile("st.shared::cluster.f32 [%0], %1;" :: "r"(a), "f"(v) : "memory");
}
__device__ __forceinline__ void cluster_sync_() {
    asm volatile("barrier.cluster.arrive.aligned;" ::: "memory");
    asm volatile("barrier.cluster.wait.aligned;" ::: "memory");
}
__device__ __forceinline__ float sigmoid_(float x) { return 1.0f / (1.0f + expf(-x)); }

// split fp32 pair -> bf16x2 hi word + bf16x2 residual word (lo = v - hi)
__device__ __forceinline__ void split2_(float v0, float v1, uint32_t& hp, uint32_t& lp) {
    asm("cvt.rn.bf16x2.f32 %0, %1, %2;" : "=r"(hp) : "f"(v1), "f"(v0));
    float h0 = __uint_as_float(hp << 16);
    float h1 = __uint_as_float(hp & 0xFFFF0000u);
    asm("cvt.rn.bf16x2.f32 %0, %1, %2;" : "=r"(lp) : "f"(v1 - h1), "f"(v0 - h0));
}

// m16n8k16 bf16 MMA, fp32 accumulate in-place
#define MMA_(c, a, b0v, b1v) \
    asm volatile("mma.sync.aligned.m16n8k16.row.col.f32.bf16.bf16.f32 " \
        "{%0,%1,%2,%3}, {%4,%5,%6,%7}, {%8,%9}, {%0,%1,%2,%3};" \
        : "+f"((c)[0]), "+f"((c)[1]), "+f"((c)[2]), "+f"((c)[3]) \
        : "r"((a)[0]), "r"((a)[1]), "r"((a)[2]), "r"((a)[3]), "r"(b0v), "r"(b1v))

// =============================================================================
// Kernel 1: per-point MLP (2->64->128) + masked max, via HMMA bf16 hi/lo split.
// grid (B*S, PSPLIT), 128 threads (4 warps). Warp w owns feature rows
// [w*32, w*32+32). D[feature][point] = W2 @ h^T, K=64, 3 split passes.
// =============================================================================
__global__ __launch_bounds__(128) void k1_mma(
    const float* __restrict__ slices, const float* __restrict__ pmask,
    const float* __restrict__ W1, const float* __restrict__ b1,
    const float* __restrict__ W2, const float* __restrict__ b2)
{
    __shared__ uint32_t Bh[128 * RS];   // bf16x2 hi words (also W2 staging)
    __shared__ uint32_t Bl[128 * RS];   // bf16x2 lo words
    __shared__ float msk[128];
    __shared__ float w1x[64], w1y[64], b1s[64];

    const int tid  = threadIdx.x;
    const int lane = tid & 31, w = tid >> 5;
    const int g = lane >> 2, ctid = lane & 3;
    const int bs = blockIdx.x;

    if (tid < 64) { w1x[tid] = W1[2 * tid]; w1y[tid] = W1[2 * tid + 1]; b1s[tid] = b1[tid]; }

    // ---- stage W2 (row tid = feature) as bf16 hi/lo into Bh/Bl ----
    {
        const float* wr = W2 + (size_t)tid * 64;
#pragma unroll 8
        for (int k = 0; k < 64; k += 2) {
            uint32_t hp, lp;
            split2_(wr[k], wr[k + 1], hp, lp);
            Bh[tid * RS + (k >> 1)] = hp;
            Bl[tid * RS + (k >> 1)] = lp;
        }
    }
    __syncthreads();

    // ---- load A fragments (W2 hi/lo) into registers: [mtile][kstep][4] ----
    uint32_t Ah[2][4][4], Al[2][4][4];
    float b2r[2][2];
#pragma unroll
    for (int mt = 0; mt < 2; mt++) {
        int rA = w * 32 + mt * 16 + g;
        b2r[mt][0] = b2[rA];
        b2r[mt][1] = b2[rA + 8];
#pragma unroll
        for (int ks = 0; ks < 4; ks++) {
            int base = rA * RS + ks * 8 + ctid;
            Ah[mt][ks][0] = Bh[base];
            Ah[mt][ks][1] = Bh[base + 8 * RS];
            Ah[mt][ks][2] = Bh[base + 4];
            Ah[mt][ks][3] = Bh[base + 8 * RS + 4];
            Al[mt][ks][0] = Bl[base];
            Al[mt][ks][1] = Bl[base + 8 * RS];
            Al[mt][ks][2] = Bl[base + 4];
            Al[mt][ks][3] = Bl[base + 8 * RS + 4];
        }
    }
    __syncthreads();   // done with staging; Bh/Bl become the point tiles

    float wmax[2][2] = {{0.f, 0.f}, {0.f, 0.f}};

    const float* sp = slices + (size_t)bs * Pn * 2;
    const float* mp = pmask + (size_t)bs * Pn;
    const int pbeg = blockIdx.y * PCHUNK;
    const int pend = pbeg + PCHUNK;

    for (int tile = 0; tile < NT1; ++tile) {
        // ---- producer: layer-1 for this thread's point -> bf16 hi/lo row ----
        const int p = pbeg + tile * 128 + tid;
        float x = 0.f, y = 0.f, m = 0.f;
        if (p < pend) {
            float2 xy = *(const float2*)(sp + 2 * p);
            x = xy.x; y = xy.y; m = mp[p];
        }
        msk[tid] = m;
#pragma unroll 8
        for (int k = 0; k < 64; k += 2) {
            float v0 = fmaxf(fmaf(w1x[k],     x, fmaf(w1y[k],     y, b1s[k])),     0.f);
            float v1 = fmaxf(fmaf(w1x[k + 1], x, fmaf(w1y[k + 1], y, b1s[k + 1])), 0.f);
            uint32_t hp, lp;
            split2_(v0, v1, hp, lp);
            Bh[tid * RS + (k >> 1)] = hp;
            Bl[tid * RS + (k >> 1)] = lp;
        }
        __syncthreads();

        // ---- consumer: warp computes its 32 feature rows x 128 points ----
#pragma unroll 4
        for (int nb = 0; nb < 16; ++nb) {
            float c0[4] = {0.f, 0.f, 0.f, 0.f};
            float c1[4] = {0.f, 0.f, 0.f, 0.f};
            const int nrow = nb * 8 + g;
#pragma unroll
            for (int ks = 0; ks < 4; ++ks) {
                int bidx = nrow * RS + ks * 8 + ctid;
                uint32_t bh0 = Bh[bidx], bh1 = Bh[bidx + 4];
                uint32_t bl0 = Bl[bidx], bl1 = Bl[bidx + 4];
                MMA_(c0, Ah[0][ks], bh0, bh1);
                MMA_(c1, Ah[1][ks], bh0, bh1);
                MMA_(c0, Ah[0][ks], bl0, bl1);
                MMA_(c1, Ah[1][ks], bl0, bl1);
                MMA_(c0, Al[0][ks], bh0, bh1);
                MMA_(c1, Al[1][ks], bh0, bh1);
            }
            // epilogue: relu(acc + b2) * mask, fold into running max
            float2 mm = *(const float2*)&msk[nb * 8 + ctid * 2];
            wmax[0][0] = fmaxf(wmax[0][0], fmaxf(c0[0] + b2r[0][0], 0.f) * mm.x);
            wmax[0][0] = fmaxf(wmax[0][0], fmaxf(c0[1] + b2r[0][0], 0.f) * mm.y);
            wmax[0][1] = fmaxf(wmax[0][1], fmaxf(c0[2] + b2r[0][1], 0.f) * mm.x);
            wmax[0][1] = fmaxf(wmax[0][1], fmaxf(c0[3] + b2r[0][1], 0.f) * mm.y);
            wmax[1][0] = fmaxf(wmax[1][0], fmaxf(c1[0] + b2r[1][0], 0.f) * mm.x);
            wmax[1][0] = fmaxf(wmax[1][0], fmaxf(c1[1] + b2r[1][0], 0.f) * mm.y);
            wmax[1][1] = fmaxf(wmax[1][1], fmaxf(c1[2] + b2r[1][1], 0.f) * mm.x);
            wmax[1][1] = fmaxf(wmax[1][1], fmaxf(c1[3] + b2r[1][1], 0.f) * mm.y);
        }
        __syncthreads();
    }

    // ---- reduce across the 4 lanes of each row-quad, write partials ----
#pragma unroll
    for (int mt = 0; mt < 2; mt++)
#pragma unroll
        for (int r = 0; r < 2; r++) {
            float v = wmax[mt][r];
            v = fmaxf(v, __shfl_xor_sync(0xFFFFFFFFu, v, 1));
            v = fmaxf(v, __shfl_xor_sync(0xFFFFFFFFu, v, 2));
            if (ctid == 0)
                d_embpart[blockIdx.y][bs][w * 32 + mt * 16 + r * 8 + g] = v;
        }
}

// =============================================================================
// Kernel 2: emb = max over partials; xg = emb . Wi + bi + bh (bwd time-reversed)
// =============================================================================
__global__ __launch_bounds__(128) void k2_inputgates(
    const float* __restrict__ Wi_f, const float* __restrict__ bi_f, const float* __restrict__ bh_f,
    const float* __restrict__ Wi_b, const float* __restrict__ bi_b, const float* __restrict__ bh_b)
{
    __shared__ float embs[128];
    const int tid = threadIdx.x;
    const int bs = blockIdx.x;
    const int b = bs / Sn, s = bs % Sn;

    float m = d_embpart[0][bs][tid];
    m = fmaxf(m, d_embpart[1][bs][tid]);
    m = fmaxf(m, d_embpart[2][bs][tid]);
    m = fmaxf(m, d_embpart[3][bs][tid]);
    embs[tid] = m;
    __syncthreads();

#pragma unroll
    for (int dir = 0; dir < 2; dir++) {
        const float* Wi = dir ? Wi_b : Wi_f;
        const float* bi = dir ? bi_b : bi_f;
        const float* bh = dir ? bh_b : bh_f;
        const int t = dir ? (Sn - 1 - s) : s;
#pragma unroll
        for (int rr = 0; rr < 4; rr++) {
            int g = rr * 128 + tid;
            const float* wr = Wi + (size_t)g * 128;
            float a = bi[g] + bh[g];
#pragma unroll 8
            for (int k = 0; k < 128; k += 4) {
                float4 w = *(const float4*)(wr + k);
                a = fmaf(w.x, embs[k], a);
                a = fmaf(w.y, embs[k + 1], a);
                a = fmaf(w.z, embs[k + 2], a);
                a = fmaf(w.w, embs[k + 3], a);
            }
            d_xg[dir][b][t][g] = a;
        }
    }
}

// =============================================================================
// Kernel 3: LSTM scan, cluster of 4 CTAs per direction.
// =============================================================================
__global__ void __cluster_dims__(4, 1, 1) __launch_bounds__(128, 1)
k3_lstm(const float* __restrict__ Wh_f, const float* __restrict__ Wh_b)
{
    extern __shared__ float sm3[];
    float* Whs  = sm3;            // [128][132]
    float* hbuf = sm3 + 16896;    // [4][128]
    float* gact = sm3 + 17408;    // [4 ranks][4 b][128] (rank 0)

    const int t = threadIdx.x;
    const int rank = blockIdx.x & 3;
    const int dir  = blockIdx.x >> 2;
    const float* Wh = dir ? Wh_b : Wh_f;

    const int R = rank * 128 + t;
    const float* wr = Wh + (size_t)R * 128;
#pragma unroll 8
    for (int k = 0; k < 128; k += 4)
        *(float4*)(Whs + t * 132 + k) = *(const float4*)(wr + k);
    for (int i = t; i < 512; i += 128) hbuf[i] = 0.f;

    float c[Bn];
#pragma unroll
    for (int b = 0; b < Bn; b++) c[b] = 0.f;

    uint32_t ga_rem[Bn];
#pragma unroll
    for (int b = 0; b < Bn; b++)
        ga_rem[b] = mapa_rank_(smem_u32_(&gact[(rank * Bn + b) * 128 + t]), 0);
    uint32_t hb_rem[4][Bn];
#pragma unroll
    for (int r = 0; r < 4; r++)
#pragma unroll
        for (int b = 0; b < Bn; b++)
            hb_rem[r][b] = mapa_rank_(smem_u32_(&hbuf[b * 128 + t]), (uint32_t)r);

    __syncthreads();
    cluster_sync_();

    for (int st = 0; st < Sn; ++st) {
        float xin[Bn];
#pragma unroll
        for (int b = 0; b < Bn; b++) xin[b] = d_xg[dir][b][st][rank * 128 + t];

        float acc[Bn];
#pragma unroll
        for (int b = 0; b < Bn; b++) acc[b] = 0.f;
#pragma unroll 4
        for (int k = 0; k < 128; k += 4) {
            float4 wv = *(const float4*)(Whs + t * 132 + k);
#pragma unroll
            for (int b = 0; b < Bn; b++) {
                float4 hv = *(const float4*)(hbuf + b * 128 + k);
                acc[b] = fmaf(wv.x, hv.x, acc[b]);
                acc[b] = fmaf(wv.y, hv.y, acc[b]);
                acc[b] = fmaf(wv.z, hv.z, acc[b]);
                acc[b] = fmaf(wv.w, hv.w, acc[b]);
            }
        }

#pragma unroll
        for (int b = 0; b < Bn; b++) {
            float gv = acc[b] + xin[b];
            float av = (rank == 2) ? tanhf(gv) : sigmoid_(gv);
            stc_f32_(ga_rem[b], av);
        }
        cluster_sync_();

        if (rank == 0) {
#pragma unroll
            for (int b = 0; b < Bn; b++) {
                float iv = gact[(0 * Bn + b) * 128 + t];
                float fv = gact[(1 * Bn + b) * 128 + t];
                float gv = gact[(2 * Bn + b) * 128 + t];
                float ov = gact[(3 * Bn + b) * 128 + t];
                float cn = fmaf(fv, c[b], iv * gv);
                c[b] = cn;
                float hv = ov * tanhf(cn);
#pragma unroll
                for (int r = 0; r < 4; r++) stc_f32_(hb_rem[r][b], hv);
            }
        }
        cluster_sync_();
    }

    if (rank == 0) {
#pragma unroll
        for (int b = 0; b < Bn; b++) d_hfinal[dir][b][t] = hbuf[b * 128 + t];
    }
}

// =============================================================================
// Kernel 4: head
// =============================================================================
__global__ __launch_bounds__(128) void k4_head(
    const float* __restrict__ W3, const float* __restrict__ b3,
    const float* __restrict__ W4, const float* __restrict__ b4,
    float* __restrict__ out)
{
    __shared__ float sf[Bn][256];
    __shared__ float red[128];
    const int tid = threadIdx.x;

    for (int idx = tid; idx < Bn * 128; idx += 128) {
        int b = idx >> 7, j = idx & 127;
        sf[b][j]       = d_hfinal[0][b][j];
        sf[b][128 + j] = d_hfinal[1][b][j];
    }
    __syncthreads();

    const float* w3r = W3 + (size_t)tid * 256;
    const float w4v = W4[tid];

    for (int b = 0; b < Bn; b++) {
        float a = b3[tid];
#pragma unroll 8
        for (int k = 0; k < 256; k += 4) {
            float4 w = *(const float4*)(w3r + k);
            a = fmaf(w.x, sf[b][k], a);
            a = fmaf(w.y, sf[b][k + 1], a);
            a = fmaf(w.z, sf[b][k + 2], a);
            a = fmaf(w.w, sf[b][k + 3], a);
        }
        float v = fmaxf(a, 0.f) * w4v;
        red[tid] = v;
        __syncthreads();
        for (int off = 64; off > 0; off >>= 1) {
            if (tid < off) red[tid] += red[tid + off];
            __syncthreads();
        }
        if (tid == 0) out[b] = red[0] + b4[0];
        __syncthreads();
    }
}

// =============================================================================
extern "C" void kernel_launch(void* const* d_in, const int* in_sizes, int n_in,
                              void* d_out, int out_size)
{
    const float* slices = (const float*)d_in[0];
    const float* pmask  = (const float*)d_in[1];
    const float* W1   = (const float*)d_in[2];
    const float* b1   = (const float*)d_in[3];
    const float* W2   = (const float*)d_in[4];
    const float* b2   = (const float*)d_in[5];
    const float* Wi_f = (const float*)d_in[6];
    const float* Wh_f = (const float*)d_in[7];
    const float* bi_f = (const float*)d_in[8];
    const float* bh_f = (const float*)d_in[9];
    const float* Wi_b = (const float*)d_in[10];
    const float* Wh_b = (const float*)d_in[11];
    const float* bi_b = (const float*)d_in[12];
    const float* bh_b = (const float*)d_in[13];
    const float* W3   = (const float*)d_in[14];
    const float* b3   = (const float*)d_in[15];
    const float* W4   = (const float*)d_in[16];
    const float* b4   = (const float*)d_in[17];
    float* out = (float*)d_out;

    cudaFuncSetAttribute(k3_lstm, cudaFuncAttributeMaxDynamicSharedMemorySize, 77824);

    k1_mma<<<dim3(Bn * Sn, PSPLIT), 128>>>(slices, pmask, W1, b1, W2, b2);
    k2_inputgates<<<Bn * Sn, 128>>>(Wi_f, bi_f, bh_f, Wi_b, bi_b, bh_b);
    k3_lstm<<<8, 128, 77824>>>(Wh_f, Wh_b);
    k4_head<<<1, 128>>>(W3, b3, W4, b4, out);
}

// round 5
// speedup vs baseline: 1.7793x; 1.0277x over previous
#include <cuda_runtime.h>
#include <cuda_bf16.h>
#include <cstdint>

#define Bn 4
#define Sn 80
#define Pn 6500
#define Hdim 128
#define PSPLIT 4
#define PCHUNK 1625   // 6500 / 4
#define NT1 13        // ceil(1625/128)
#define RS 35         // SMEM row stride in 32-bit words — conflict-free

// dynamic-smem word offsets for k1 (double-buffered)
#define O_BH(buf) ((buf) * 4480)            // 128*RS words each
#define O_BL(buf) (8960 + (buf) * 4480)
#define O_MSK(buf) (17920 + (buf) * 128)
#define O_W1X 18176
#define O_W1Y 18240
#define O_B1  18304
#define SM1_WORDS 18368
#define SM1_BYTES (SM1_WORDS * 4)           // 73472

// ---------------- scratch ----------------
__device__ float d_embpart[PSPLIT][Bn * Sn][128];
__device__ float d_xg[2][Bn][Sn][4 * Hdim];
__device__ float d_hfinal[2][Bn][Hdim];

// ---------------- helpers ----------------
__device__ __forceinline__ uint32_t smem_u32_(const void* p) {
    return (uint32_t)__cvta_generic_to_shared(p);
}
__device__ __forceinline__ uint32_t mapa_rank_(uint32_t a, uint32_t r) {
    uint32_t d;
    asm("mapa.shared::cluster.u32 %0, %1, %2;" : "=r"(d) : "r"(a), "r"(r));
    return d;
}
__device__ __forceinline__ void stc_f32_(uint32_t a, float v) {
    asm volatile("st.shared::cluster.f32 [%0], %1;" :: "r"(a), "f"(v) : "memory");
}
__device__ __forceinline__ void cluster_sync_() {
    asm volatile("barrier.cluster.arrive.aligned;" ::: "memory");
    asm volatile("barrier.cluster.wait.aligned;" ::: "memory");
}
__device__ __forceinline__ float sigmoid_(float x) { return 1.0f / (1.0f + expf(-x)); }

// split fp32 pair -> bf16x2 hi word + bf16x2 residual word
__device__ __forceinline__ void split2_(float v0, float v1, uint32_t& hp, uint32_t& lp) {
    asm("cvt.rn.bf16x2.f32 %0, %1, %2;" : "=r"(hp) : "f"(v1), "f"(v0));
    float h0 = __uint_as_float(hp << 16);
    float h1 = __uint_as_float(hp & 0xFFFF0000u);
    asm("cvt.rn.bf16x2.f32 %0, %1, %2;" : "=r"(lp) : "f"(v1 - h1), "f"(v0 - h0));
}

// m16n8k16 bf16 MMA, fp32 accumulate in-place
#define MMA_(c, a, b0v, b1v) \
    asm volatile("mma.sync.aligned.m16n8k16.row.col.f32.bf16.bf16.f32 " \
        "{%0,%1,%2,%3}, {%4,%5,%6,%7}, {%8,%9}, {%0,%1,%2,%3};" \
        : "+f"((c)[0]), "+f"((c)[1]), "+f"((c)[2]), "+f"((c)[3]) \
        : "r"((a)[0]), "r"((a)[1]), "r"((a)[2]), "r"((a)[3]), "r"(b0v), "r"(b1v))

// packed f32x2 fma (Blackwell)
__device__ __forceinline__ void fma2_(uint64_t& acc, uint64_t a, uint64_t b) {
    asm("fma.rn.f32x2 %0, %1, %2, %0;" : "+l"(acc) : "l"(a), "l"(b));
}

// =============================================================================
// Kernel 1: per-point MLP (2->64->128) + masked max, HMMA bf16 hi/lo split,
// double-buffered: produce tile t+1 (FMA pipe) while MMA'ing tile t (tensor).
// grid (B*S, PSPLIT), 128 threads (4 warps). Warp w owns feature rows w*32..+32.
// =============================================================================
__global__ __launch_bounds__(128) void k1_mma(
    const float* __restrict__ slices, const float* __restrict__ pmask,
    const float* __restrict__ W1, const float* __restrict__ b1,
    const float* __restrict__ W2, const float* __restrict__ b2)
{
    extern __shared__ uint32_t smw[];
    float* w1x = (float*)(smw + O_W1X);
    float* w1y = (float*)(smw + O_W1Y);
    float* b1s = (float*)(smw + O_B1);

    const int tid  = threadIdx.x;
    const int lane = tid & 31, w = tid >> 5;
    const int g = lane >> 2, ctid = lane & 3;
    const int bs = blockIdx.x;

    if (tid < 64) { w1x[tid] = W1[2 * tid]; w1y[tid] = W1[2 * tid + 1]; b1s[tid] = b1[tid]; }

    // ---- stage W2 bf16 hi/lo into buffer 0 (scratch) ----
    {
        const float* wr = W2 + (size_t)tid * 64;
#pragma unroll 8
        for (int k = 0; k < 64; k += 2) {
            uint32_t hp, lp;
            split2_(wr[k], wr[k + 1], hp, lp);
            smw[O_BH(0) + tid * RS + (k >> 1)] = hp;
            smw[O_BL(0) + tid * RS + (k >> 1)] = lp;
        }
    }
    __syncthreads();

    // ---- A fragments (W2 hi/lo) into registers: [mtile][kstep][4] ----
    uint32_t Ah[2][4][4], Al[2][4][4];
    float b2r[2][2];
#pragma unroll
    for (int mt = 0; mt < 2; mt++) {
        int rA = w * 32 + mt * 16 + g;
        b2r[mt][0] = b2[rA];
        b2r[mt][1] = b2[rA + 8];
#pragma unroll
        for (int ks = 0; ks < 4; ks++) {
            int base = rA * RS + ks * 8 + ctid;
            Ah[mt][ks][0] = smw[O_BH(0) + base];
            Ah[mt][ks][1] = smw[O_BH(0) + base + 8 * RS];
            Ah[mt][ks][2] = smw[O_BH(0) + base + 4];
            Ah[mt][ks][3] = smw[O_BH(0) + base + 8 * RS + 4];
            Al[mt][ks][0] = smw[O_BL(0) + base];
            Al[mt][ks][1] = smw[O_BL(0) + base + 8 * RS];
            Al[mt][ks][2] = smw[O_BL(0) + base + 4];
            Al[mt][ks][3] = smw[O_BL(0) + base + 8 * RS + 4];
        }
    }
    __syncthreads();   // staging done; buffers become point tiles

    const float* sp = slices + (size_t)bs * Pn * 2;
    const float* mp = pmask + (size_t)bs * Pn;
    const int pbeg = blockIdx.y * PCHUNK;
    const int pend = pbeg + PCHUNK;

    // producer lambda: layer-1 + split for one 128-pt tile into buffer buf
    auto produce = [&](int tile, int buf) {
        const int p = pbeg + tile * 128 + tid;
        float x = 0.f, y = 0.f, m = 0.f;
        if (p < pend) {
            float2 xy = *(const float2*)(sp + 2 * p);
            x = xy.x; y = xy.y; m = mp[p];
        }
        ((float*)(smw + O_MSK(buf)))[tid] = m;
        uint32_t* bh = smw + O_BH(buf) + tid * RS;
        uint32_t* bl = smw + O_BL(buf) + tid * RS;
#pragma unroll 8
        for (int k = 0; k < 64; k += 2) {
            float v0 = fmaxf(fmaf(w1x[k],     x, fmaf(w1y[k],     y, b1s[k])),     0.f);
            float v1 = fmaxf(fmaf(w1x[k + 1], x, fmaf(w1y[k + 1], y, b1s[k + 1])), 0.f);
            uint32_t hp, lp;
            split2_(v0, v1, hp, lp);
            bh[k >> 1] = hp;
            bl[k >> 1] = lp;
        }
    };

    float wmax[2][2] = {{0.f, 0.f}, {0.f, 0.f}};

    produce(0, 0);
    __syncthreads();

    for (int tile = 0; tile < NT1; ++tile) {
        const int cur = tile & 1, nxt = cur ^ 1;
        if (tile + 1 < NT1) produce(tile + 1, nxt);   // FMA pipe (independent buffer)

        const uint32_t* Bh = smw + O_BH(cur);
        const uint32_t* Bl = smw + O_BL(cur);
        const float* msk = (const float*)(smw + O_MSK(cur));

#pragma unroll 4
        for (int nb = 0; nb < 16; ++nb) {
            float c0[4] = {0.f, 0.f, 0.f, 0.f};
            float c1[4] = {0.f, 0.f, 0.f, 0.f};
            const int nrow = nb * 8 + g;
#pragma unroll
            for (int ks = 0; ks < 4; ++ks) {
                int bidx = nrow * RS + ks * 8 + ctid;
                uint32_t bh0 = Bh[bidx], bh1 = Bh[bidx + 4];
                uint32_t bl0 = Bl[bidx], bl1 = Bl[bidx + 4];
                MMA_(c0, Ah[0][ks], bh0, bh1);
                MMA_(c1, Ah[1][ks], bh0, bh1);
                MMA_(c0, Ah[0][ks], bl0, bl1);
                MMA_(c1, Ah[1][ks], bl0, bl1);
                MMA_(c0, Al[0][ks], bh0, bh1);
                MMA_(c1, Al[1][ks], bh0, bh1);
            }
            float2 mm = *(const float2*)&msk[nb * 8 + ctid * 2];
            wmax[0][0] = fmaxf(wmax[0][0], fmaxf(c0[0] + b2r[0][0], 0.f) * mm.x);
            wmax[0][0] = fmaxf(wmax[0][0], fmaxf(c0[1] + b2r[0][0], 0.f) * mm.y);
            wmax[0][1] = fmaxf(wmax[0][1], fmaxf(c0[2] + b2r[0][1], 0.f) * mm.x);
            wmax[0][1] = fmaxf(wmax[0][1], fmaxf(c0[3] + b2r[0][1], 0.f) * mm.y);
            wmax[1][0] = fmaxf(wmax[1][0], fmaxf(c1[0] + b2r[1][0], 0.f) * mm.x);
            wmax[1][0] = fmaxf(wmax[1][0], fmaxf(c1[1] + b2r[1][0], 0.f) * mm.y);
            wmax[1][1] = fmaxf(wmax[1][1], fmaxf(c1[2] + b2r[1][1], 0.f) * mm.x);
            wmax[1][1] = fmaxf(wmax[1][1], fmaxf(c1[3] + b2r[1][1], 0.f) * mm.y);
        }
        __syncthreads();   // nxt fully produced; cur free for overwrite
    }

    // reduce across the 4 lanes of each row-quad, write partials
#pragma unroll
    for (int mt = 0; mt < 2; mt++)
#pragma unroll
        for (int r = 0; r < 2; r++) {
            float v = wmax[mt][r];
            v = fmaxf(v, __shfl_xor_sync(0xFFFFFFFFu, v, 1));
            v = fmaxf(v, __shfl_xor_sync(0xFFFFFFFFu, v, 2));
            if (ctid == 0)
                d_embpart[blockIdx.y][bs][w * 32 + mt * 16 + r * 8 + g] = v;
        }
}

// =============================================================================
// Kernel 2: emb = max over partials; xg = emb . Wi + bi + bh (bwd time-reversed)
// =============================================================================
__global__ __launch_bounds__(128) void k2_inputgates(
    const float* __restrict__ Wi_f, const float* __restrict__ bi_f, const float* __restrict__ bh_f,
    const float* __restrict__ Wi_b, const float* __restrict__ bi_b, const float* __restrict__ bh_b)
{
    __shared__ float embs[128];
    const int tid = threadIdx.x;
    const int bs = blockIdx.x;
    const int b = bs / Sn, s = bs % Sn;

    float m = d_embpart[0][bs][tid];
    m = fmaxf(m, d_embpart[1][bs][tid]);
    m = fmaxf(m, d_embpart[2][bs][tid]);
    m = fmaxf(m, d_embpart[3][bs][tid]);
    embs[tid] = m;
    __syncthreads();

#pragma unroll
    for (int dir = 0; dir < 2; dir++) {
        const float* Wi = dir ? Wi_b : Wi_f;
        const float* bi = dir ? bi_b : bi_f;
        const float* bh = dir ? bh_b : bh_f;
        const int t = dir ? (Sn - 1 - s) : s;
#pragma unroll
        for (int rr = 0; rr < 4; rr++) {
            int g = rr * 128 + tid;
            const float* wr = Wi + (size_t)g * 128;
            float a = bi[g] + bh[g];
#pragma unroll 8
            for (int k = 0; k < 128; k += 4) {
                float4 w = *(const float4*)(wr + k);
                a = fmaf(w.x, embs[k], a);
                a = fmaf(w.y, embs[k + 1], a);
                a = fmaf(w.z, embs[k + 2], a);
                a = fmaf(w.w, embs[k + 3], a);
            }
            d_xg[dir][b][t][g] = a;
        }
    }
}

// =============================================================================
// Kernel 3: LSTM scan, cluster of 4 CTAs per direction, f32x2 inner product.
// =============================================================================
__global__ void __cluster_dims__(4, 1, 1) __launch_bounds__(128, 1)
k3_lstm(const float* __restrict__ Wh_f, const float* __restrict__ Wh_b)
{
    extern __shared__ float sm3[];
    float* Whs  = sm3;            // [128][132]
    float* hbuf = sm3 + 16896;    // [4][128]
    float* gact = sm3 + 17408;    // [4 ranks][4 b][128] (rank 0)

    const int t = threadIdx.x;
    const int rank = blockIdx.x & 3;
    const int dir  = blockIdx.x >> 2;
    const float* Wh = dir ? Wh_b : Wh_f;

    const int R = rank * 128 + t;
    const float* wr = Wh + (size_t)R * 128;
#pragma unroll 8
    for (int k = 0; k < 128; k += 4)
        *(float4*)(Whs + t * 132 + k) = *(const float4*)(wr + k);
    for (int i = t; i < 512; i += 128) hbuf[i] = 0.f;

    float c[Bn];
#pragma unroll
    for (int b = 0; b < Bn; b++) c[b] = 0.f;

    uint32_t ga_rem[Bn];
#pragma unroll
    for (int b = 0; b < Bn; b++)
        ga_rem[b] = mapa_rank_(smem_u32_(&gact[(rank * Bn + b) * 128 + t]), 0);
    uint32_t hb_rem[4][Bn];
#pragma unroll
    for (int r = 0; r < 4; r++)
#pragma unroll
        for (int b = 0; b < Bn; b++)
            hb_rem[r][b] = mapa_rank_(smem_u32_(&hbuf[b * 128 + t]), (uint32_t)r);

    const uint64_t* wp = (const uint64_t*)(Whs + t * 132);   // 528B offset, 8-aligned

    __syncthreads();
    cluster_sync_();

    for (int st = 0; st < Sn; ++st) {
        float xin[Bn];
#pragma unroll
        for (int b = 0; b < Bn; b++) xin[b] = d_xg[dir][b][st][rank * 128 + t];

        uint64_t acc2[Bn];
#pragma unroll
        for (int b = 0; b < Bn; b++) acc2[b] = 0ull;
#pragma unroll 8
        for (int k2 = 0; k2 < 64; k2++) {
            uint64_t wv = wp[k2];
#pragma unroll
            for (int b = 0; b < Bn; b++) {
                uint64_t hv = *(const uint64_t*)(hbuf + b * 128 + k2 * 2);
                fma2_(acc2[b], wv, hv);
            }
        }

#pragma unroll
        for (int b = 0; b < Bn; b++) {
            float lo = __uint_as_float((uint32_t)acc2[b]);
            float hi = __uint_as_float((uint32_t)(acc2[b] >> 32));
            float gv = lo + hi + xin[b];
            float av = (rank == 2) ? tanhf(gv) : sigmoid_(gv);
            stc_f32_(ga_rem[b], av);
        }
        cluster_sync_();

        if (rank == 0) {
#pragma unroll
            for (int b = 0; b < Bn; b++) {
                float iv = gact[(0 * Bn + b) * 128 + t];
                float fv = gact[(1 * Bn + b) * 128 + t];
                float gv = gact[(2 * Bn + b) * 128 + t];
                float ov = gact[(3 * Bn + b) * 128 + t];
                float cn = fmaf(fv, c[b], iv * gv);
                c[b] = cn;
                float hv = ov * tanhf(cn);
#pragma unroll
                for (int r = 0; r < 4; r++) stc_f32_(hb_rem[r][b], hv);
            }
        }
        cluster_sync_();
    }

    if (rank == 0) {
#pragma unroll
        for (int b = 0; b < Bn; b++) d_hfinal[dir][b][t] = hbuf[b * 128 + t];
    }
}

// =============================================================================
// Kernel 4: head — grid=4 (batch), 256 threads (thread = half a W3 row).
// =============================================================================
__global__ __launch_bounds__(256) void k4_head(
    const float* __restrict__ W3, const float* __restrict__ b3,
    const float* __restrict__ W4, const float* __restrict__ b4,
    float* __restrict__ out)
{
    __shared__ float sf[256];
    __shared__ float red[128];
    const int tid = threadIdx.x;
    const int b = blockIdx.x;

    if (tid < 128) {
        sf[tid]       = d_hfinal[0][b][tid];
        sf[128 + tid] = d_hfinal[1][b][tid];
    }
    __syncthreads();

    const int r = tid >> 1, half = tid & 1;
    const float* w3r = W3 + (size_t)r * 256 + half * 128;
    const float* xf = sf + half * 128;

    float a = 0.f;
#pragma unroll 8
    for (int k = 0; k < 128; k += 4) {
        float4 w = *(const float4*)(w3r + k);
        a = fmaf(w.x, xf[k], a);
        a = fmaf(w.y, xf[k + 1], a);
        a = fmaf(w.z, xf[k + 2], a);
        a = fmaf(w.w, xf[k + 3], a);
    }
    a += __shfl_xor_sync(0xFFFFFFFFu, a, 1);
    if (half == 0) red[r] = fmaxf(a + b3[r], 0.f) * W4[r];
    __syncthreads();
    for (int off = 64; off > 0; off >>= 1) {
        if (tid < off) red[tid] += red[tid + off];
        __syncthreads();
    }
    if (tid == 0) out[b] = red[0] + b4[0];
}

// =============================================================================
extern "C" void kernel_launch(void* const* d_in, const int* in_sizes, int n_in,
                              void* d_out, int out_size)
{
    const float* slices = (const float*)d_in[0];
    const float* pmask  = (const float*)d_in[1];
    const float* W1   = (const float*)d_in[2];
    const float* b1   = (const float*)d_in[3];
    const float* W2   = (const float*)d_in[4];
    const float* b2   = (const float*)d_in[5];
    const float* Wi_f = (const float*)d_in[6];
    const float* Wh_f = (const float*)d_in[7];
    const float* bi_f = (const float*)d_in[8];
    const float* bh_f = (const float*)d_in[9];
    const float* Wi_b = (const float*)d_in[10];
    const float* Wh_b = (const float*)d_in[11];
    const float* bi_b = (const float*)d_in[12];
    const float* bh_b = (const float*)d_in[13];
    const float* W3   = (const float*)d_in[14];
    const float* b3   = (const float*)d_in[15];
    const float* W4   = (const float*)d_in[16];
    const float* b4   = (const float*)d_in[17];
    float* out = (float*)d_out;

    cudaFuncSetAttribute(k1_mma,  cudaFuncAttributeMaxDynamicSharedMemorySize, SM1_BYTES);
    cudaFuncSetAttribute(k3_lstm, cudaFuncAttributeMaxDynamicSharedMemorySize, 77824);

    k1_mma<<<dim3(Bn * Sn, PSPLIT), 128, SM1_BYTES>>>(slices, pmask, W1, b1, W2, b2);
    k2_inputgates<<<Bn * Sn, 128>>>(Wi_f, bi_f, bh_f, Wi_b, bi_b, bh_b);
    k3_lstm<<<8, 128, 77824>>>(Wh_f, Wh_b);
    k4_head<<<4, 256>>>(W3, b3, W4, b4, out);
}

// round 6
// speedup vs baseline: 2.4120x; 1.3555x over previous
#include <cuda_runtime.h>
#include <cuda_fp16.h>
#include <cstdint>

#define Bn 4
#define Sn 80
#define Pn 6500
#define Hdim 128
#define PSPLIT 4
#define PCHUNK 1625   // 6500 / 4
#define NT1 13        // ceil(1625/128)
#define RS 35         // SMEM row stride in 32-bit words — conflict-free

// ---------------- scratch ----------------
__device__ float d_embpart[PSPLIT][Bn * Sn][128];
__device__ float d_xg[2][Bn][Sn][4 * Hdim];
__device__ float d_hfinal[2][Bn][Hdim];

// ---------------- helpers ----------------
__device__ __forceinline__ uint32_t smem_u32_(const void* p) {
    return (uint32_t)__cvta_generic_to_shared(p);
}
__device__ __forceinline__ uint32_t mapa_rank_(uint32_t a, uint32_t r) {
    uint32_t d;
    asm("mapa.shared::cluster.u32 %0, %1, %2;" : "=r"(d) : "r"(a), "r"(r));
    return d;
}
__device__ __forceinline__ void stc_f32_(uint32_t a, float v) {
    asm volatile("st.shared::cluster.f32 [%0], %1;" :: "r"(a), "f"(v) : "memory");
}
__device__ __forceinline__ void cluster_sync_() {
    asm volatile("barrier.cluster.arrive.aligned;" ::: "memory");
    asm volatile("barrier.cluster.wait.aligned;" ::: "memory");
}
__device__ __forceinline__ float sigmoid_(float x) { return 1.0f / (1.0f + expf(-x)); }

// pack two fp32 -> f16x2 word (v0 in low half)
__device__ __forceinline__ uint32_t packh2_(float v0, float v1) {
    __half2 h = __floats2half2_rn(v0, v1);
    return *reinterpret_cast<uint32_t*>(&h);
}

// m16n8k16 fp16 MMA, fp32 accumulate in-place
#define MMA_(c, a, b0v, b1v) \
    asm volatile("mma.sync.aligned.m16n8k16.row.col.f32.f16.f16.f32 " \
        "{%0,%1,%2,%3}, {%4,%5,%6,%7}, {%8,%9}, {%0,%1,%2,%3};" \
        : "+f"((c)[0]), "+f"((c)[1]), "+f"((c)[2]), "+f"((c)[3]) \
        : "r"((a)[0]), "r"((a)[1]), "r"((a)[2]), "r"((a)[3]), "r"(b0v), "r"(b1v))

// packed f32x2 fma (Blackwell)
__device__ __forceinline__ void fma2_(uint64_t& acc, uint64_t a, uint64_t b) {
    asm("fma.rn.f32x2 %0, %1, %2, %0;" : "+l"(acc) : "l"(a), "l"(b));
}

// =============================================================================
// Kernel 1: per-point MLP (2->64->128) + masked max, single-pass fp16 HMMA,
// double-buffered. grid (B*S, PSPLIT), 128 threads (4 warps).
// Warp w owns feature rows [w*32, w*32+32). D[feature][point] = W2 @ h^T, K=64.
// =============================================================================
__global__ __launch_bounds__(128) void k1_mma(
    const float* __restrict__ slices, const float* __restrict__ pmask,
    const float* __restrict__ W1, const float* __restrict__ b1,
    const float* __restrict__ W2, const float* __restrict__ b2)
{
    __shared__ uint32_t Bf[2][128 * RS];   // f16x2 point tiles (buf0 also W2 staging)
    __shared__ float mskS[2][128];
    __shared__ float w1x[64], w1y[64], b1s[64];

    const int tid  = threadIdx.x;
    const int lane = tid & 31, w = tid >> 5;
    const int g = lane >> 2, ctid = lane & 3;
    const int bs = blockIdx.x;

    if (tid < 64) { w1x[tid] = W1[2 * tid]; w1y[tid] = W1[2 * tid + 1]; b1s[tid] = b1[tid]; }

    // ---- stage W2 fp16 into buffer 0 (scratch) ----
    {
        const float* wr = W2 + (size_t)tid * 64;
#pragma unroll 8
        for (int k = 0; k < 64; k += 2)
            Bf[0][tid * RS + (k >> 1)] = packh2_(wr[k], wr[k + 1]);
    }
    __syncthreads();

    // ---- A fragments (W2 fp16) into registers: [mtile][kstep][4] ----
    uint32_t Ah[2][4][4];
    float b2r[2][2];
#pragma unroll
    for (int mt = 0; mt < 2; mt++) {
        int rA = w * 32 + mt * 16 + g;
        b2r[mt][0] = b2[rA];
        b2r[mt][1] = b2[rA + 8];
#pragma unroll
        for (int ks = 0; ks < 4; ks++) {
            int base = rA * RS + ks * 8 + ctid;
            Ah[mt][ks][0] = Bf[0][base];
            Ah[mt][ks][1] = Bf[0][base + 8 * RS];
            Ah[mt][ks][2] = Bf[0][base + 4];
            Ah[mt][ks][3] = Bf[0][base + 8 * RS + 4];
        }
    }
    __syncthreads();   // staging done; buffers become point tiles

    const float* sp = slices + (size_t)bs * Pn * 2;
    const float* mp = pmask + (size_t)bs * Pn;
    const int pbeg = blockIdx.y * PCHUNK;
    const int pend = pbeg + PCHUNK;

    // producer: layer-1 + fp16 pack for one 128-pt tile into buffer buf
    auto produce = [&](int tile, int buf) {
        const int p = pbeg + tile * 128 + tid;
        float x = 0.f, y = 0.f, m = 0.f;
        if (p < pend) {
            float2 xy = *(const float2*)(sp + 2 * p);
            x = xy.x; y = xy.y; m = mp[p];
        }
        mskS[buf][tid] = m;
        uint32_t* br = &Bf[buf][tid * RS];
#pragma unroll 8
        for (int k = 0; k < 64; k += 2) {
            float v0 = fmaxf(fmaf(w1x[k],     x, fmaf(w1y[k],     y, b1s[k])),     0.f);
            float v1 = fmaxf(fmaf(w1x[k + 1], x, fmaf(w1y[k + 1], y, b1s[k + 1])), 0.f);
            br[k >> 1] = packh2_(v0, v1);
        }
    };

    float wmax[2][2] = {{0.f, 0.f}, {0.f, 0.f}};

    produce(0, 0);
    __syncthreads();

    for (int tile = 0; tile < NT1; ++tile) {
        const int cur = tile & 1, nxt = cur ^ 1;
        if (tile + 1 < NT1) produce(tile + 1, nxt);

        const uint32_t* Bp = Bf[cur];
        const float* msk = mskS[cur];

        // two point-blocks per iteration -> 4 independent accumulator chains
#pragma unroll 2
        for (int nbp = 0; nbp < 8; ++nbp) {
            float cA0[4] = {0.f, 0.f, 0.f, 0.f};
            float cA1[4] = {0.f, 0.f, 0.f, 0.f};
            float cB0[4] = {0.f, 0.f, 0.f, 0.f};
            float cB1[4] = {0.f, 0.f, 0.f, 0.f};
            const int nrA = nbp * 16 + g;       // point block 2*nbp
            const int nrB = nrA + 8;            // point block 2*nbp+1
#pragma unroll
            for (int ks = 0; ks < 4; ++ks) {
                int ia = nrA * RS + ks * 8 + ctid;
                int ib = nrB * RS + ks * 8 + ctid;
                uint32_t a0 = Bp[ia], a1 = Bp[ia + 4];
                uint32_t b0 = Bp[ib], b1 = Bp[ib + 4];
                MMA_(cA0, Ah[0][ks], a0, a1);
                MMA_(cB0, Ah[0][ks], b0, b1);
                MMA_(cA1, Ah[1][ks], a0, a1);
                MMA_(cB1, Ah[1][ks], b0, b1);
            }
            float2 mA = *(const float2*)&msk[nbp * 16 + ctid * 2];
            float2 mB = *(const float2*)&msk[nbp * 16 + 8 + ctid * 2];
            wmax[0][0] = fmaxf(wmax[0][0], fmaxf(cA0[0] + b2r[0][0], 0.f) * mA.x);
            wmax[0][0] = fmaxf(wmax[0][0], fmaxf(cA0[1] + b2r[0][0], 0.f) * mA.y);
            wmax[0][1] = fmaxf(wmax[0][1], fmaxf(cA0[2] + b2r[0][1], 0.f) * mA.x);
            wmax[0][1] = fmaxf(wmax[0][1], fmaxf(cA0[3] + b2r[0][1], 0.f) * mA.y);
            wmax[1][0] = fmaxf(wmax[1][0], fmaxf(cA1[0] + b2r[1][0], 0.f) * mA.x);
            wmax[1][0] = fmaxf(wmax[1][0], fmaxf(cA1[1] + b2r[1][0], 0.f) * mA.y);
            wmax[1][1] = fmaxf(wmax[1][1], fmaxf(cA1[2] + b2r[1][1], 0.f) * mA.x);
            wmax[1][1] = fmaxf(wmax[1][1], fmaxf(cA1[3] + b2r[1][1], 0.f) * mA.y);
            wmax[0][0] = fmaxf(wmax[0][0], fmaxf(cB0[0] + b2r[0][0], 0.f) * mB.x);
            wmax[0][0] = fmaxf(wmax[0][0], fmaxf(cB0[1] + b2r[0][0], 0.f) * mB.y);
            wmax[0][1] = fmaxf(wmax[0][1], fmaxf(cB0[2] + b2r[0][1], 0.f) * mB.x);
            wmax[0][1] = fmaxf(wmax[0][1], fmaxf(cB0[3] + b2r[0][1], 0.f) * mB.y);
            wmax[1][0] = fmaxf(wmax[1][0], fmaxf(cB1[0] + b2r[1][0], 0.f) * mB.x);
            wmax[1][0] = fmaxf(wmax[1][0], fmaxf(cB1[1] + b2r[1][0], 0.f) * mB.y);
            wmax[1][1] = fmaxf(wmax[1][1], fmaxf(cB1[2] + b2r[1][1], 0.f) * mB.x);
            wmax[1][1] = fmaxf(wmax[1][1], fmaxf(cB1[3] + b2r[1][1], 0.f) * mB.y);
        }
        __syncthreads();
    }

    // reduce across the 4 lanes of each row-quad, write partials
#pragma unroll
    for (int mt = 0; mt < 2; mt++)
#pragma unroll
        for (int r = 0; r < 2; r++) {
            float v = wmax[mt][r];
            v = fmaxf(v, __shfl_xor_sync(0xFFFFFFFFu, v, 1));
            v = fmaxf(v, __shfl_xor_sync(0xFFFFFFFFu, v, 2));
            if (ctid == 0)
                d_embpart[blockIdx.y][bs][w * 32 + mt * 16 + r * 8 + g] = v;
        }
}

// =============================================================================
// Kernel 2: emb = max over partials; xg = emb . Wi + bi + bh (bwd time-reversed)
// =============================================================================
__global__ __launch_bounds__(128) void k2_inputgates(
    const float* __restrict__ Wi_f, const float* __restrict__ bi_f, const float* __restrict__ bh_f,
    const float* __restrict__ Wi_b, const float* __restrict__ bi_b, const float* __restrict__ bh_b)
{
    __shared__ float embs[128];
    const int tid = threadIdx.x;
    const int bs = blockIdx.x;
    const int b = bs / Sn, s = bs % Sn;

    float m = d_embpart[0][bs][tid];
    m = fmaxf(m, d_embpart[1][bs][tid]);
    m = fmaxf(m, d_embpart[2][bs][tid]);
    m = fmaxf(m, d_embpart[3][bs][tid]);
    embs[tid] = m;
    __syncthreads();

#pragma unroll
    for (int dir = 0; dir < 2; dir++) {
        const float* Wi = dir ? Wi_b : Wi_f;
        const float* bi = dir ? bi_b : bi_f;
        const float* bh = dir ? bh_b : bh_f;
        const int t = dir ? (Sn - 1 - s) : s;
#pragma unroll
        for (int rr = 0; rr < 4; rr++) {
            int g = rr * 128 + tid;
            const float* wr = Wi + (size_t)g * 128;
            float a = bi[g] + bh[g];
#pragma unroll 8
            for (int k = 0; k < 128; k += 4) {
                float4 w = *(const float4*)(wr + k);
                a = fmaf(w.x, embs[k], a);
                a = fmaf(w.y, embs[k + 1], a);
                a = fmaf(w.z, embs[k + 2], a);
                a = fmaf(w.w, embs[k + 3], a);
            }
            d_xg[dir][b][t][g] = a;
        }
    }
}

// =============================================================================
// Kernel 3: LSTM scan, cluster of 4 CTAs per direction, f32x2 inner product.
// =============================================================================
__global__ void __cluster_dims__(4, 1, 1) __launch_bounds__(128, 1)
k3_lstm(const float* __restrict__ Wh_f, const float* __restrict__ Wh_b)
{
    extern __shared__ float sm3[];
    float* Whs  = sm3;            // [128][132]
    float* hbuf = sm3 + 16896;    // [4][128]
    float* gact = sm3 + 17408;    // [4 ranks][4 b][128] (rank 0)

    const int t = threadIdx.x;
    const int rank = blockIdx.x & 3;
    const int dir  = blockIdx.x >> 2;
    const float* Wh = dir ? Wh_b : Wh_f;

    const int R = rank * 128 + t;
    const float* wr = Wh + (size_t)R * 128;
#pragma unroll 8
    for (int k = 0; k < 128; k += 4)
        *(float4*)(Whs + t * 132 + k) = *(const float4*)(wr + k);
    for (int i = t; i < 512; i += 128) hbuf[i] = 0.f;

    float c[Bn];
#pragma unroll
    for (int b = 0; b < Bn; b++) c[b] = 0.f;

    uint32_t ga_rem[Bn];
#pragma unroll
    for (int b = 0; b < Bn; b++)
        ga_rem[b] = mapa_rank_(smem_u32_(&gact[(rank * Bn + b) * 128 + t]), 0);
    uint32_t hb_rem[4][Bn];
#pragma unroll
    for (int r = 0; r < 4; r++)
#pragma unroll
        for (int b = 0; b < Bn; b++)
            hb_rem[r][b] = mapa_rank_(smem_u32_(&hbuf[b * 128 + t]), (uint32_t)r);

    const uint64_t* wp = (const uint64_t*)(Whs + t * 132);   // 528B offset, 8-aligned

    __syncthreads();
    cluster_sync_();

    for (int st = 0; st < Sn; ++st) {
        float xin[Bn];
#pragma unroll
        for (int b = 0; b < Bn; b++) xin[b] = d_xg[dir][b][st][rank * 128 + t];

        uint64_t acc2[Bn];
#pragma unroll
        for (int b = 0; b < Bn; b++) acc2[b] = 0ull;
#pragma unroll 8
        for (int k2 = 0; k2 < 64; k2++) {
            uint64_t wv = wp[k2];
#pragma unroll
            for (int b = 0; b < Bn; b++) {
                uint64_t hv = *(const uint64_t*)(hbuf + b * 128 + k2 * 2);
                fma2_(acc2[b], wv, hv);
            }
        }

#pragma unroll
        for (int b = 0; b < Bn; b++) {
            float lo = __uint_as_float((uint32_t)acc2[b]);
            float hi = __uint_as_float((uint32_t)(acc2[b] >> 32));
            float gv = lo + hi + xin[b];
            float av = (rank == 2) ? tanhf(gv) : sigmoid_(gv);
            stc_f32_(ga_rem[b], av);
        }
        cluster_sync_();

        if (rank == 0) {
#pragma unroll
            for (int b = 0; b < Bn; b++) {
                float iv = gact[(0 * Bn + b) * 128 + t];
                float fv = gact[(1 * Bn + b) * 128 + t];
                float gv = gact[(2 * Bn + b) * 128 + t];
                float ov = gact[(3 * Bn + b) * 128 + t];
                float cn = fmaf(fv, c[b], iv * gv);
                c[b] = cn;
                float hv = ov * tanhf(cn);
#pragma unroll
                for (int r = 0; r < 4; r++) stc_f32_(hb_rem[r][b], hv);
            }
        }
        cluster_sync_();
    }

    if (rank == 0) {
#pragma unroll
        for (int b = 0; b < Bn; b++) d_hfinal[dir][b][t] = hbuf[b * 128 + t];
    }
}

// =============================================================================
// Kernel 4: head — grid=4 (batch), 512 threads (thread = quarter W3 row).
// =============================================================================
__global__ __launch_bounds__(512) void k4_head(
    const float* __restrict__ W3, const float* __restrict__ b3,
    const float* __restrict__ W4, const float* __restrict__ b4,
    float* __restrict__ out)
{
    __shared__ float sf[256];
    __shared__ float red[128];
    const int tid = threadIdx.x;
    const int b = blockIdx.x;

    if (tid < 128) {
        sf[tid]       = d_hfinal[0][b][tid];
        sf[128 + tid] = d_hfinal[1][b][tid];
    }
    __syncthreads();

    const int r = tid >> 2, q = tid & 3;
    const float* w3r = W3 + (size_t)r * 256 + q * 64;
    const float* xf = sf + q * 64;

    float a = 0.f;
#pragma unroll 8
    for (int k = 0; k < 64; k += 4) {
        float4 wv = *(const float4*)(w3r + k);
        a = fmaf(wv.x, xf[k], a);
        a = fmaf(wv.y, xf[k + 1], a);
        a = fmaf(wv.z, xf[k + 2], a);
        a = fmaf(wv.w, xf[k + 3], a);
    }
    a += __shfl_xor_sync(0xFFFFFFFFu, a, 1);
    a += __shfl_xor_sync(0xFFFFFFFFu, a, 2);
    if (q == 0) red[r] = fmaxf(a + b3[r], 0.f) * W4[r];
    __syncthreads();
    for (int off = 64; off > 0; off >>= 1) {
        if (tid < off) red[tid] += red[tid + off];
        __syncthreads();
    }
    if (tid == 0) out[b] = red[0] + b4[0];
}

// =============================================================================
extern "C" void kernel_launch(void* const* d_in, const int* in_sizes, int n_in,
                              void* d_out, int out_size)
{
    const float* slices = (const float*)d_in[0];
    const float* pmask  = (const float*)d_in[1];
    const float* W1   = (const float*)d_in[2];
    const float* b1   = (const float*)d_in[3];
    const float* W2   = (const float*)d_in[4];
    const float* b2   = (const float*)d_in[5];
    const float* Wi_f = (const float*)d_in[6];
    const float* Wh_f = (const float*)d_in[7];
    const float* bi_f = (const float*)d_in[8];
    const float* bh_f = (const float*)d_in[9];
    const float* Wi_b = (const float*)d_in[10];
    const float* Wh_b = (const float*)d_in[11];
    const float* bi_b = (const float*)d_in[12];
    const float* bh_b = (const float*)d_in[13];
    const float* W3   = (const float*)d_in[14];
    const float* b3   = (const float*)d_in[15];
    const float* W4   = (const float*)d_in[16];
    const float* b4   = (const float*)d_in[17];
    float* out = (float*)d_out;

    cudaFuncSetAttribute(k3_lstm, cudaFuncAttributeMaxDynamicSharedMemorySize, 77824);

    k1_mma<<<dim3(Bn * Sn, PSPLIT), 128>>>(slices, pmask, W1, b1, W2, b2);
    k2_inputgates<<<Bn * Sn, 128>>>(Wi_f, bi_f, bh_f, Wi_b, bi_b, bh_b);
    k3_lstm<<<8, 128, 77824>>>(Wh_f, Wh_b);
    k4_head<<<4, 512>>>(W3, b3, W4, b4, out);
}